// round 6
// baseline (speedup 1.0000x reference)
#include <cuda_runtime.h>
#include <stdint.h>

// Problem constants (from reference setup_inputs)
#define BB 1024
#define RR 192
// pair offsets k = 1..96 (circular), 96 bits of adjacency mask per thread
#define NMW 3

#define ALPHA 1.0f
#define BETA  1.0f
#define GAMMA 0.5f
#define DELTA 0.3f

// Scratch (no allocations allowed)
__device__ float    g_partials[BB * 4];
__device__ unsigned g_pairmask[RR * NMW];

// ---------------------------------------------------------------------------
// Pre-kernel: bake per-(thread t, offset k) adjacency bit.
// Pair for (t, k): {t, (t+k)%R}; reference mask uses adj[min][max] (triu).
// 192 blocks x 96 threads; ballot packs 96 bits into 3 words per t.
// ---------------------------------------------------------------------------
__global__ void fp_build_mask(const int* __restrict__ adj) {
    int t  = blockIdx.x;
    int kk = threadIdx.x;        // kk in [0,96), k = kk+1
    int k  = kk + 1;
    int a = t;
    int b = t + k; if (b >= RR) b -= RR;
    int i = a < b ? a : b;
    int j = a < b ? b : a;
    int bit = (adj[i * RR + j] > 0) ? 1 : 0;
    unsigned bal = __ballot_sync(0xffffffffu, bit);
    if ((kk & 31) == 0) g_pairmask[t * NMW + (kk >> 5)] = bal;
}

// ---------------------------------------------------------------------------
// Main kernel: one block per batch. Thread t owns room i=t in registers,
// streams room j = t+k from duplicated smem arrays (no wrap, no conflicts).
// Overlap on all pairs; center distance via bit-trick rsqrt (2 Newton iters),
// accumulated only where the precomputed adjacency bit is set.
// ---------------------------------------------------------------------------
__global__ __launch_bounds__(RR, 4) void fp_main(
    const float2* __restrict__ pu, const float2* __restrict__ su,
    const float2* __restrict__ tp, const float2* __restrict__ ts)
{
    __shared__ float sm[6][2 * RR];   // x, y, x+w, y+h, cx, cy (duplicated)
    __shared__ float red[6][4];

    const int t = threadIdx.x;
    const int b = blockIdx.x;
    const int base = b * RR + t;

    float2 p = pu[base];
    float2 s = su[base];
    float2 q = tp[base];
    float2 z = ts[base];

    float xi  = p.x, yi = p.y;
    float xwi = p.x + s.x;
    float yhi = p.y + s.y;
    float cxi = fmaf(0.5f, s.x, p.x);
    float cyi = fmaf(0.5f, s.y, p.y);

    sm[0][t] = xi;  sm[0][t + RR] = xi;
    sm[1][t] = yi;  sm[1][t + RR] = yi;
    sm[2][t] = xwi; sm[2][t + RR] = xwi;
    sm[3][t] = yhi; sm[3][t + RR] = yhi;
    sm[4][t] = cxi; sm[4][t + RR] = cxi;
    sm[5][t] = cyi; sm[5][t + RR] = cyi;

    // MSE partials for this thread's room
    float dpx = p.x - q.x, dpy = p.y - q.y;
    float pos_acc = dpx * dpx + dpy * dpy;
    float dsx = s.x - z.x, dsy = s.y - z.y;
    float size_acc = dsx * dsx + dsy * dsy;

    unsigned m0 = g_pairmask[t * NMW + 0];
    unsigned m1 = g_pairmask[t * NMW + 1];
    unsigned m2 = g_pairmask[t * NMW + 2];

    __syncthreads();

    float ovl = 0.0f, adjacc = 0.0f;

#define PAIR_STEP(JJ, MBIT) do {                                              \
        int jj = (JJ);                                                        \
        float xj  = sm[0][jj];                                                \
        float yj  = sm[1][jj];                                                \
        float xwj = sm[2][jj];                                                \
        float yhj = sm[3][jj];                                                \
        float cxj = sm[4][jj];                                                \
        float cyj = sm[5][jj];                                                \
        float ow = fminf(xwi, xwj) - fmaxf(xi, xj);                           \
        ow = fmaxf(ow, 0.0f);                                                 \
        float oh = fminf(yhi, yhj) - fmaxf(yi, yj);                           \
        oh = fmaxf(oh, 0.0f);                                                 \
        ovl = fmaf(ow, oh, ovl);                                              \
        float dx = cxi - cxj;                                                 \
        float dy = cyi - cyj;                                                 \
        float sq = fmaf(dx, dx, dy * dy);                                     \
        sq = fmaxf(sq, 1e-30f);                                               \
        float yr = __uint_as_float(0x5f3759dfu - (__float_as_uint(sq) >> 1)); \
        float xh = 0.5f * sq;                                                 \
        yr = yr * fmaf(-xh, yr * yr, 1.5f);                                   \
        yr = yr * fmaf(-xh, yr * yr, 1.5f);                                   \
        float dist = sq * yr;                                                 \
        adjacc += (MBIT) ? dist : 0.0f;                                       \
    } while (0)

    // k = 1..32  (mask word m0, bit kk)
#pragma unroll
    for (int kk = 0; kk < 32; ++kk)
        PAIR_STEP(t + 1 + kk, (m0 >> kk) & 1u);
    // k = 33..64 (mask word m1)
#pragma unroll
    for (int kk = 0; kk < 32; ++kk)
        PAIR_STEP(t + 33 + kk, (m1 >> kk) & 1u);
    // k = 65..95 (mask word m2, bits 0..30)
#pragma unroll
    for (int kk = 0; kk < 31; ++kk)
        PAIR_STEP(t + 65 + kk, (m2 >> kk) & 1u);
    // k = 96: each pair at circular distance 96 appears twice; only t<96 does it
    if (t < 96)
        PAIR_STEP(t + 96, (m2 >> 31) & 1u);

#undef PAIR_STEP

    // -------- block reduction (deterministic, no atomics) --------
    const unsigned FULL = 0xffffffffu;
#pragma unroll
    for (int o = 16; o > 0; o >>= 1) {
        pos_acc  += __shfl_down_sync(FULL, pos_acc,  o);
        size_acc += __shfl_down_sync(FULL, size_acc, o);
        ovl      += __shfl_down_sync(FULL, ovl,      o);
        adjacc   += __shfl_down_sync(FULL, adjacc,   o);
    }
    int warp = t >> 5, lane = t & 31;
    if (lane == 0) {
        red[warp][0] = pos_acc;
        red[warp][1] = size_acc;
        red[warp][2] = ovl;
        red[warp][3] = adjacc;
    }
    __syncthreads();
    if (t == 0) {
        float s0 = 0.f, s1 = 0.f, s2 = 0.f, s3 = 0.f;
#pragma unroll
        for (int w = 0; w < 6; ++w) {
            s0 += red[w][0]; s1 += red[w][1];
            s2 += red[w][2]; s3 += red[w][3];
        }
        g_partials[b * 4 + 0] = s0;
        g_partials[b * 4 + 1] = s1;
        g_partials[b * 4 + 2] = s2;
        g_partials[b * 4 + 3] = s3;
    }
}

// ---------------------------------------------------------------------------
// Final deterministic reduction over 1024 per-batch partials + scalar epilogue
// ---------------------------------------------------------------------------
__global__ void fp_finalize(float* __restrict__ out) {
    __shared__ float red[32][4];
    int t = threadIdx.x;            // 1024 threads: one per batch
    float v0 = g_partials[t * 4 + 0];
    float v1 = g_partials[t * 4 + 1];
    float v2 = g_partials[t * 4 + 2];
    float v3 = g_partials[t * 4 + 3];
    const unsigned FULL = 0xffffffffu;
#pragma unroll
    for (int o = 16; o > 0; o >>= 1) {
        v0 += __shfl_down_sync(FULL, v0, o);
        v1 += __shfl_down_sync(FULL, v1, o);
        v2 += __shfl_down_sync(FULL, v2, o);
        v3 += __shfl_down_sync(FULL, v3, o);
    }
    int warp = t >> 5, lane = t & 31;
    if (lane == 0) {
        red[warp][0] = v0; red[warp][1] = v1;
        red[warp][2] = v2; red[warp][3] = v3;
    }
    __syncthreads();
    if (t < 32) {
        v0 = red[t][0]; v1 = red[t][1]; v2 = red[t][2]; v3 = red[t][3];
#pragma unroll
        for (int o = 16; o > 0; o >>= 1) {
            v0 += __shfl_down_sync(FULL, v0, o);
            v1 += __shfl_down_sync(FULL, v1, o);
            v2 += __shfl_down_sync(FULL, v2, o);
            v3 += __shfl_down_sync(FULL, v3, o);
        }
        if (t == 0) {
            float pos_loss  = v0 * (1.0f / (float)(BB * RR * 2));
            float size_loss = v1 * (1.0f / (float)(BB * RR * 2));
            float ovl_pen   = v2 * (1.0f / (float)BB);
            float adj_loss  = v3 * (1.0f / (float)BB);
            float total = ALPHA * pos_loss + BETA * size_loss
                        + GAMMA * ovl_pen + DELTA * adj_loss;
            out[0] = total;
            out[1] = pos_loss;
            out[2] = size_loss;
            out[3] = ovl_pen;
            out[4] = adj_loss;
        }
    }
}

// ---------------------------------------------------------------------------
// Harness entry point
// ---------------------------------------------------------------------------
extern "C" void kernel_launch(void* const* d_in, const int* in_sizes, int n_in,
                              void* d_out, int out_size) {
    (void)in_sizes; (void)n_in; (void)out_size;
    const float2* pu = (const float2*)d_in[0];
    const float2* su = (const float2*)d_in[1];
    const float2* tp = (const float2*)d_in[2];
    const float2* ts = (const float2*)d_in[3];
    const int*   adj = (const int*)d_in[4];
    float* out = (float*)d_out;

    fp_build_mask<<<RR, 96>>>(adj);
    fp_main<<<BB, RR>>>(pu, su, tp, ts);
    fp_finalize<<<1, 1024>>>(out);
}

// round 7
// speedup vs baseline: 1.0618x; 1.0618x over previous
#include <cuda_runtime.h>
#include <stdint.h>

// Problem constants (from reference setup_inputs)
#define BB 1024
#define RR 192
#define NMW 3          // 96 pair-offset bits per thread -> 3 words

#define ALPHA 1.0f
#define BETA  1.0f
#define GAMMA 0.5f
#define DELTA 0.3f

// Scratch (no allocations allowed). Zero-initialized by CUDA runtime.
__device__ float    g_partials[BB * 4];
__device__ unsigned g_pairmask[RR * NMW];
__device__ unsigned g_count;   // self-resetting last-block ticket

// ---------------------------------------------------------------------------
// Pre-kernel: bake per-(thread t, offset k) adjacency bit.
// Flat: g = t*96 + kk, kk in [0,96), k = kk+1. 96 % 32 == 0 so every warp's
// 32 bits belong to one row -> ballot packs directly into g_pairmask[g>>5].
// 18 blocks x 1024 threads = 18432 = RR*96 exactly.
// ---------------------------------------------------------------------------
__global__ void fp_build_mask(const int* __restrict__ adj) {
    int g  = blockIdx.x * 1024 + threadIdx.x;
    int t  = g / 96;
    int kk = g % 96;
    int k  = kk + 1;
    int b2 = t + k; if (b2 >= RR) b2 -= RR;
    int i = t < b2 ? t : b2;
    int j = t < b2 ? b2 : t;
    int bit = (adj[i * RR + j] > 0) ? 1 : 0;
    unsigned bal = __ballot_sync(0xffffffffu, bit);
    if ((g & 31) == 0) g_pairmask[g >> 5] = bal;
}

// ---------------------------------------------------------------------------
// Main kernel: one block per batch. Thread t owns room i=t in registers,
// streams room j = t+k from duplicated float2 smem (LDS.64, no wrap, no
// conflicts). Overlap on all pairs; center distance via MUFU rsqrt.
// Last block (atomic ticket) performs the deterministic final reduction.
// ---------------------------------------------------------------------------
__global__ __launch_bounds__(RR, 4) void fp_main(
    const float2* __restrict__ pu, const float2* __restrict__ su,
    const float2* __restrict__ tp, const float2* __restrict__ ts,
    float* __restrict__ out)
{
    __shared__ float2 sxy[2 * RR];   // (x, y)
    __shared__ float2 swh[2 * RR];   // (x+w, y+h)
    __shared__ float2 sc [2 * RR];   // (cx, cy)
    __shared__ float  red[6][4];
    __shared__ int    is_last;

    const int t = threadIdx.x;
    const int b = blockIdx.x;
    const int base = b * RR + t;

    float2 p = pu[base];
    float2 s = su[base];
    float2 q = tp[base];
    float2 z = ts[base];

    const float xi  = p.x, yi = p.y;
    const float xwi = p.x + s.x;
    const float yhi = p.y + s.y;
    const float cxi = fmaf(0.5f, s.x, p.x);
    const float cyi = fmaf(0.5f, s.y, p.y);

    float2 vxy = make_float2(xi,  yi);
    float2 vwh = make_float2(xwi, yhi);
    float2 vc  = make_float2(cxi, cyi);
    sxy[t] = vxy; sxy[t + RR] = vxy;
    swh[t] = vwh; swh[t + RR] = vwh;
    sc [t] = vc;  sc [t + RR] = vc;

    // MSE partials for this thread's room
    float dpx = p.x - q.x, dpy = p.y - q.y;
    float pos_acc = fmaf(dpx, dpx, dpy * dpy);
    float dsx = s.x - z.x, dsy = s.y - z.y;
    float size_acc = fmaf(dsx, dsx, dsy * dsy);

    const unsigned m0 = g_pairmask[t * NMW + 0];
    const unsigned m1 = g_pairmask[t * NMW + 1];
    const unsigned m2 = g_pairmask[t * NMW + 2];

    __syncthreads();

    float ovl = 0.0f, adjacc = 0.0f;

#define PAIR_STEP(JJ, MBIT) do {                                              \
        int jj = (JJ);                                                        \
        float2 aj = sxy[jj];                                                  \
        float2 bj = swh[jj];                                                  \
        float2 cj = sc [jj];                                                  \
        float ow = fminf(xwi, bj.x) - fmaxf(xi, aj.x);                        \
        float oh = fminf(yhi, bj.y) - fmaxf(yi, aj.y);                        \
        ow = fmaxf(ow, 0.0f);                                                 \
        oh = fmaxf(oh, 0.0f);                                                 \
        ovl = fmaf(ow, oh, ovl);                                              \
        float dx = cxi - cj.x;                                                \
        float dy = cyi - cj.y;                                                \
        float sq = fmaf(dx, dx, dy * dy);                                     \
        sq = fmaxf(sq, 1e-30f);                                               \
        float r;                                                              \
        asm("rsqrt.approx.f32 %0, %1;" : "=f"(r) : "f"(sq));                  \
        float dist = sq * r;                                                  \
        adjacc += (MBIT) ? dist : 0.0f;                                       \
    } while (0)

    // k = 1..32  (mask word m0)
#pragma unroll
    for (int kk = 0; kk < 32; ++kk)
        PAIR_STEP(t + 1 + kk, m0 & (1u << kk));
    // k = 33..64 (mask word m1)
#pragma unroll
    for (int kk = 0; kk < 32; ++kk)
        PAIR_STEP(t + 33 + kk, m1 & (1u << kk));
    // k = 65..95 (mask word m2, bits 0..30)
#pragma unroll
    for (int kk = 0; kk < 31; ++kk)
        PAIR_STEP(t + 65 + kk, m2 & (1u << kk));
    // k = 96: circular distance 96 pairs appear twice; only t<96 keeps one
    if (t < 96)
        PAIR_STEP(t + 96, m2 & 0x80000000u);

#undef PAIR_STEP

    // -------- block reduction (deterministic, no atomics) --------
    const unsigned FULL = 0xffffffffu;
#pragma unroll
    for (int o = 16; o > 0; o >>= 1) {
        pos_acc  += __shfl_down_sync(FULL, pos_acc,  o);
        size_acc += __shfl_down_sync(FULL, size_acc, o);
        ovl      += __shfl_down_sync(FULL, ovl,      o);
        adjacc   += __shfl_down_sync(FULL, adjacc,   o);
    }
    int warp = t >> 5, lane = t & 31;
    if (lane == 0) {
        red[warp][0] = pos_acc;
        red[warp][1] = size_acc;
        red[warp][2] = ovl;
        red[warp][3] = adjacc;
    }
    __syncthreads();
    if (t == 0) {
        float s0 = 0.f, s1 = 0.f, s2 = 0.f, s3 = 0.f;
#pragma unroll
        for (int w = 0; w < 6; ++w) {
            s0 += red[w][0]; s1 += red[w][1];
            s2 += red[w][2]; s3 += red[w][3];
        }
        g_partials[b * 4 + 0] = s0;
        g_partials[b * 4 + 1] = s1;
        g_partials[b * 4 + 2] = s2;
        g_partials[b * 4 + 3] = s3;
        __threadfence();
        unsigned old = atomicAdd(&g_count, 1u);
        is_last = (old == (unsigned)(BB - 1)) ? 1 : 0;
    }
    __syncthreads();

    // -------- last block: deterministic final reduction + epilogue --------
    if (is_last) {
        float v0 = 0.f, v1 = 0.f, v2 = 0.f, v3 = 0.f;
        // fixed strided order: deterministic regardless of which block is last
        for (int i = t; i < BB; i += RR) {
            v0 += g_partials[i * 4 + 0];
            v1 += g_partials[i * 4 + 1];
            v2 += g_partials[i * 4 + 2];
            v3 += g_partials[i * 4 + 3];
        }
#pragma unroll
        for (int o = 16; o > 0; o >>= 1) {
            v0 += __shfl_down_sync(FULL, v0, o);
            v1 += __shfl_down_sync(FULL, v1, o);
            v2 += __shfl_down_sync(FULL, v2, o);
            v3 += __shfl_down_sync(FULL, v3, o);
        }
        __syncthreads();   // red[] reuse is safe (prior read done pre-barrier)
        if (lane == 0) {
            red[warp][0] = v0; red[warp][1] = v1;
            red[warp][2] = v2; red[warp][3] = v3;
        }
        __syncthreads();
        if (t == 0) {
            float s0 = 0.f, s1 = 0.f, s2 = 0.f, s3 = 0.f;
#pragma unroll
            for (int w = 0; w < 6; ++w) {
                s0 += red[w][0]; s1 += red[w][1];
                s2 += red[w][2]; s3 += red[w][3];
            }
            float pos_loss  = s0 * (1.0f / (float)(BB * RR * 2));
            float size_loss = s1 * (1.0f / (float)(BB * RR * 2));
            float ovl_pen   = s2 * (1.0f / (float)BB);
            float adj_loss  = s3 * (1.0f / (float)BB);
            out[0] = ALPHA * pos_loss + BETA * size_loss
                   + GAMMA * ovl_pen + DELTA * adj_loss;
            out[1] = pos_loss;
            out[2] = size_loss;
            out[3] = ovl_pen;
            out[4] = adj_loss;
            g_count = 0;   // reset for next graph replay (deterministic)
        }
    }
}

// ---------------------------------------------------------------------------
// Harness entry point
// ---------------------------------------------------------------------------
extern "C" void kernel_launch(void* const* d_in, const int* in_sizes, int n_in,
                              void* d_out, int out_size) {
    (void)in_sizes; (void)n_in; (void)out_size;
    const float2* pu = (const float2*)d_in[0];
    const float2* su = (const float2*)d_in[1];
    const float2* tp = (const float2*)d_in[2];
    const float2* ts = (const float2*)d_in[3];
    const int*   adj = (const int*)d_in[4];
    float* out = (float*)d_out;

    fp_build_mask<<<18, 1024>>>(adj);
    fp_main<<<BB, RR>>>(pu, su, tp, ts, out);
}